// round 3
// baseline (speedup 1.0000x reference)
#include <cuda_runtime.h>
#include <math.h>

// Problem constants
#define NMAX 16000
#define EMAX 256000

// ---------------- static device scratch (no allocation allowed) ----------------
__device__ float g_xvT [3*NMAX*64];   // xv transposed [c][n][u]
__device__ float g_f0  [NMAX*192];    // concat(xs, vnorm)
__device__ float g_pre_s[NMAX*128];
__device__ float g_pre_v[3*NMAX*64];  // [c][n][u]
__device__ float g_h1  [NMAX*192];
__device__ float g_g   [NMAX*192];
__device__ float g_xv2T[3*NMAX*64];
__device__ float g_xs3 [NMAX*128];
__device__ float g_xv3 [3*NMAX*64];   // [c][n][u]
__device__ float g_ns  [NMAX*192];
__device__ float g_nv  [3*NMAX*192];  // [c][n][row]
__device__ int   g_ei  [2*EMAX];      // normalized int32 edge index
__device__ int   g_is64;

// ---------------- edge-index dtype detection ----------------
// int64 values < 2^31: every odd 32-bit word is 0. int32 data: odd words are
// random node indices, overwhelmingly nonzero.
__global__ void detect_kernel(const int* __restrict__ ei_raw) {
    if (threadIdx.x == 0 && blockIdx.x == 0) {
        int nz = 0;
        for (int i = 1; i < 256; i += 2) nz += (ei_raw[i] != 0);
        g_is64 = (nz == 0) ? 1 : 0;
    }
}

__global__ void convert_kernel(const int* __restrict__ ei_raw, int total) {
    int is64 = g_is64;
    for (int idx = blockIdx.x * blockDim.x + threadIdx.x; idx < total;
         idx += gridDim.x * blockDim.x) {
        g_ei[idx] = is64 ? ei_raw[2 * idx] : ei_raw[idx];
    }
}

// ---------------- prep: build xvT, f0 = [xs, vnorm] ----------------
__global__ void prep_kernel(const float* __restrict__ x, int N) {
    int total = N * 192;
    for (int idx = blockIdx.x * blockDim.x + threadIdx.x; idx < total;
         idx += gridDim.x * blockDim.x) {
        int n = idx / 192, i = idx - n * 192;
        if (i < 128) {
            g_f0[n * 192 + i] = x[n * 320 + i];
        } else {
            int u = i - 128;
            float a = x[n * 320 + 128 + 3 * u + 0];
            float b = x[n * 320 + 128 + 3 * u + 1];
            float c = x[n * 320 + 128 + 3 * u + 2];
            g_xvT[(0 * N + n) * 64 + u] = a;
            g_xvT[(1 * N + n) * 64 + u] = b;
            g_xvT[(2 * N + n) * 64 + u] = c;
            g_f0[n * 192 + i] = sqrtf(a * a + b * b + c * c + 1e-12f);
        }
    }
}

// ---------------- gate: xv2 = xv * g[:,128:] ----------------
__global__ void gate_kernel(int N) {
    int total = 3 * N * 64;
    for (int idx = blockIdx.x * blockDim.x + threadIdx.x; idx < total;
         idx += gridDim.x * blockDim.x) {
        int rem = idx % (N * 64);
        int n = rem / 64, u = rem - n * 64;
        g_xv2T[idx] = g_xvT[idx] * g_g[n * 192 + 128 + u];
    }
}

// ---------------- zero accumulators ----------------
__global__ void zero_kernel(int N) {
    int t1 = N * 192;
    int t2 = 3 * N * 192;
    int total = t1 + t2;
    for (int idx = blockIdx.x * blockDim.x + threadIdx.x; idx < total;
         idx += gridDim.x * blockDim.x) {
        if (idx < t1) g_ns[idx] = 0.f;
        else          g_nv[idx - t1] = 0.f;
    }
}

// ---------------- generic SGEMM: C = act(X[M,K] @ W[K,O] * scale + bias) ----------------
// BM=BN=64, BK=16, 256 threads, 4x4 per thread.
// out_mode 0: C[m*ldc + o]
// out_mode 1: vector interleave: c=m/nnodes, n=m%nnodes -> C[n*640 + 256 + o*3 + c]
__global__ void gemm_kernel(const float* __restrict__ X, int ldx,
                            const float* __restrict__ W, int ldw,
                            float* __restrict__ C,
                            int M, int K, int O,
                            float scale, const float* __restrict__ bias,
                            int act, int out_mode, int ldc, int nnodes) {
    __shared__ __align__(16) float sX[16][64];
    __shared__ __align__(16) float sW[16][64];
    int bm = blockIdx.y * 64, bo = blockIdx.x * 64;
    int tid = threadIdx.x;
    int tr = tid >> 4, tc = tid & 15;
    float acc[4][4];
#pragma unroll
    for (int i = 0; i < 4; i++)
#pragma unroll
        for (int j = 0; j < 4; j++) acc[i][j] = 0.f;

    for (int k0 = 0; k0 < K; k0 += 16) {
#pragma unroll
        for (int l = 0; l < 4; l++) {
            int i = tid + l * 256;
            int r = i >> 4, c = i & 15;
            sX[c][r] = X[(long long)(bm + r) * ldx + k0 + c];
        }
#pragma unroll
        for (int l = 0; l < 4; l++) {
            int i = tid + l * 256;
            int r = i >> 6, c = i & 63;
            sW[r][c] = W[(k0 + r) * ldw + bo + c];
        }
        __syncthreads();
#pragma unroll
        for (int k = 0; k < 16; k++) {
            float4 xv4 = *reinterpret_cast<const float4*>(&sX[k][tr * 4]);
            float4 wv4 = *reinterpret_cast<const float4*>(&sW[k][tc * 4]);
            float xr[4] = {xv4.x, xv4.y, xv4.z, xv4.w};
            float wc[4] = {wv4.x, wv4.y, wv4.z, wv4.w};
#pragma unroll
            for (int i = 0; i < 4; i++)
#pragma unroll
                for (int j = 0; j < 4; j++) acc[i][j] += xr[i] * wc[j];
        }
        __syncthreads();
    }

#pragma unroll
    for (int i = 0; i < 4; i++) {
        int m = bm + tr * 4 + i;
#pragma unroll
        for (int j = 0; j < 4; j++) {
            int o = bo + tc * 4 + j;
            float v = acc[i][j] * scale;
            if (bias) v += bias[o];
            if (act == 1) v = v / (1.f + expf(-v));   // silu
            if (out_mode == 0) {
                C[(long long)m * ldc + o] = v;
            } else {
                int cc = m / nnodes;
                int n = m - cc * nnodes;
                C[(long long)n * 640 + 256 + o * 3 + cc] = v;
            }
        }
    }
}

// ---------------- fused edge kernel ----------------
// 512 threads, 32 edges per tile, all 4 MLP weights staged in SMEM.
#define ETILE 32
#define ETHREADS 512
#define EDGE_SMEM_FLOATS (1024 + 12288 + 10240 + 12288 + ETILE*320 + ETILE*32 + ETILE*32 + ETILE*32 + ETILE*4)
#define EDGE_SMEM_BYTES (EDGE_SMEM_FLOATS*4 + 2*ETILE*4)

__global__ void edge_kernel(const float* __restrict__ edge_attr,
                            const float* __restrict__ edge_sh,
                            const float* __restrict__ Wf1, const float* __restrict__ Wf2,
                            const float* __restrict__ Wl1, const float* __restrict__ Wl2,
                            int E, int N) {
    extern __shared__ float sm[];
    float* sWf1 = sm;                 // 32*32   = 1024
    float* sWf2 = sWf1 + 1024;        // 32*384  = 12288
    float* sWl1 = sWf2 + 12288;       // 320*32  = 10240
    float* sWl2 = sWl1 + 10240;       // 32*384  = 12288
    float* s0   = sWl2 + 12288;       // 32*320
    float* sea  = s0 + ETILE * 320;   // 32*32
    float* shf  = sea + ETILE * 32;   // 32*32
    float* shl  = shf + ETILE * 32;   // 32*32
    float* ssh  = shl + ETILE * 32;   // 32*4
    int*   sidx = (int*)(ssh + ETILE * 4); // 2*32 ints

    int tid = threadIdx.x;
    for (int i = tid; i < 1024;  i += ETHREADS) sWf1[i] = Wf1[i];
    for (int i = tid; i < 12288; i += ETHREADS) sWf2[i] = Wf2[i];
    for (int i = tid; i < 10240; i += ETHREADS) sWl1[i] = Wl1[i];
    for (int i = tid; i < 12288; i += ETHREADS) sWl2[i] = Wl2[i];

    const float c0 = 0.5f, c1 = 0.86602540378443865f;
    const float inv3 = 1.f / 3.f;
    const float invs32 = 0.17677669529663687f;    // 1/sqrt(32)
    const float invs320 = 0.05590169943749474f;   // 1/sqrt(320)
    const float invs3 = 0.57735026918962576f;     // 1/sqrt(3)
    const float ln2 = 0.69314718055994531f;

    int ntiles = (E + ETILE - 1) / ETILE;
    for (int tile = blockIdx.x; tile < ntiles; tile += gridDim.x) {
        int e0 = tile * ETILE;
        int cnt = min(ETILE, E - e0);
        __syncthreads();   // protect smem reuse across tiles (also covers weight load)
        if (tid < ETILE) {
            int e = e0 + tid;
            int valid = (tid < cnt);
            sidx[tid]         = valid ? g_ei[e]     : 0;
            sidx[ETILE + tid] = valid ? g_ei[E + e] : 0;
        }
        if (tid < ETILE * 4) {
            int t = tid >> 2, q = tid & 3;
            ssh[t * 4 + q] = (t < cnt) ? edge_sh[(long long)(e0 + t) * 4 + q] : 0.f;
        }
        for (int i = tid; i < ETILE * 32; i += ETHREADS) {
            int t = i >> 5, q = i & 31;
            sea[i] = (t < cnt) ? edge_attr[(long long)(e0 + t) * 32 + q] : 0.f;
        }
        __syncthreads();

        // build s0 = [pre_s[dst], pre_s[dst], ip1]
        for (int i = tid; i < ETILE * 320; i += ETHREADS) {
            int t = i / 320, q = i - t * 320;
            float v = 0.f;
            if (t < cnt) {
                int d = sidx[t], s = sidx[ETILE + t];
                if (q < 128)       v = g_pre_s[(long long)d * 128 + q];
                else if (q < 256)  v = g_pre_s[(long long)d * 128 + q - 128];
                else {
                    int u = q - 256;
                    float acc = 0.f;
#pragma unroll
                    for (int c = 0; c < 3; c++)
                        acc += g_pre_v[((long long)c * N + d) * 64 + u] *
                               g_pre_v[((long long)c * N + s) * 64 + u];
                    v = acc * inv3;
                }
            }
            s0[t * 320 + q] = v;
        }
        __syncthreads();

        // hf = ssp(edge_attr @ Wf1 / sqrt(32))
        for (int i = tid; i < ETILE * 32; i += ETHREADS) {
            int t = i >> 5, j = i & 31;
            float acc = 0.f;
#pragma unroll 8
            for (int q = 0; q < 32; q++) acc += sea[t * 32 + q] * sWf1[q * 32 + j];
            acc *= invs32;
            shf[i] = fmaxf(acc, 0.f) + log1pf(expf(-fabsf(acc))) - ln2;
        }
        // hl = ssp(s0 @ Wl1 / sqrt(320))
        for (int i = tid; i < ETILE * 32; i += ETHREADS) {
            int t = i >> 5, j = i & 31;
            float acc = 0.f;
#pragma unroll 8
            for (int q = 0; q < 320; q++) acc += s0[t * 320 + q] * sWl1[q * 32 + j];
            acc *= invs320;
            shl[i] = fmaxf(acc, 0.f) + log1pf(expf(-fabsf(acc))) - ln2;
        }
        __syncthreads();

        // w[t][o] = (hf@Wf2)(hl@Wl2)/32, fused scatter
        for (int i = tid; i < ETILE * 384; i += ETHREADS) {
            int t = i / 384, o = i - t * 384;
            if (t >= cnt) continue;
            int d = sidx[t], s = sidx[ETILE + t];
            float wf = 0.f, wl = 0.f;
#pragma unroll 8
            for (int j = 0; j < 32; j++) {
                wf += shf[t * 32 + j] * sWf2[j * 384 + o];
                wl += shl[t * 32 + j] * sWl2[j * 384 + o];
            }
            float w = wf * wl * (invs32 * invs32);   // /32
            float sh0 = ssh[t * 4 + 0];
            if (o < 128) {
                float hs = g_xs3[(long long)s * 128 + o];
                atomicAdd(&g_ns[(long long)d * 192 + o], c0 * w * hs * sh0);
            } else if (o < 256) {
                int u = o - 128;
                float hs = g_xs3[(long long)s * 128 + u];
                float base = c1 * w * hs;
#pragma unroll
                for (int c = 0; c < 3; c++)
                    atomicAdd(&g_nv[((long long)c * N + d) * 192 + u], base * ssh[t * 4 + 1 + c]);
            } else if (o < 320) {
                int u = o - 256;
                float base = c1 * w * sh0;
#pragma unroll
                for (int c = 0; c < 3; c++) {
                    float hv = g_xv3[((long long)c * N + s) * 64 + u];
                    atomicAdd(&g_nv[((long long)c * N + d) * 192 + 128 + u], base * hv);
                }
            } else {
                int u = o - 320;
                float dot = 0.f;
#pragma unroll
                for (int c = 0; c < 3; c++)
                    dot += g_xv3[((long long)c * N + s) * 64 + u] * ssh[t * 4 + 1 + c];
                atomicAdd(&g_ns[(long long)d * 192 + 128 + u], c0 * w * dot * invs3);
            }
        }
    }
}

// ---------------- launch ----------------
extern "C" void kernel_launch(void* const* d_in, const int* in_sizes, int n_in,
                              void* d_out, int out_size) {
    const float*     x      = (const float*)d_in[0];
    const int*       ei_raw = (const int*)d_in[1];
    const float*     ea     = (const float*)d_in[2];
    const float*     esh    = (const float*)d_in[3];
    const float*     Wpre_s = (const float*)d_in[4];
    const float*     bpre_s = (const float*)d_in[5];
    const float*     Wpre_v = (const float*)d_in[6];
    const float*     Wg1    = (const float*)d_in[7];
    const float*     bg1    = (const float*)d_in[8];
    const float*     Wg2    = (const float*)d_in[9];
    const float*     bg2    = (const float*)d_in[10];
    const float*     Wn_s   = (const float*)d_in[11];
    const float*     bn_s   = (const float*)d_in[12];
    const float*     Wn_v   = (const float*)d_in[13];
    const float*     Wf1    = (const float*)d_in[14];
    const float*     Wf2    = (const float*)d_in[15];
    const float*     Wl1    = (const float*)d_in[16];
    const float*     Wl2    = (const float*)d_in[17];
    const float*     Wo_s   = (const float*)d_in[18];
    const float*     bo_s   = (const float*)d_in[19];
    const float*     Wo_v   = (const float*)d_in[20];

    int N = in_sizes[0] / 320;
    int E = in_sizes[1] / 2;
    float* out = (float*)d_out;

    float *p_xvT, *p_f0, *p_pre_s, *p_pre_v, *p_h1, *p_g, *p_xv2T, *p_xs3, *p_xv3, *p_ns, *p_nv;
    cudaGetSymbolAddress((void**)&p_xvT,  g_xvT);
    cudaGetSymbolAddress((void**)&p_f0,   g_f0);
    cudaGetSymbolAddress((void**)&p_pre_s,g_pre_s);
    cudaGetSymbolAddress((void**)&p_pre_v,g_pre_v);
    cudaGetSymbolAddress((void**)&p_h1,   g_h1);
    cudaGetSymbolAddress((void**)&p_g,    g_g);
    cudaGetSymbolAddress((void**)&p_xv2T, g_xv2T);
    cudaGetSymbolAddress((void**)&p_xs3,  g_xs3);
    cudaGetSymbolAddress((void**)&p_xv3,  g_xv3);
    cudaGetSymbolAddress((void**)&p_ns,   g_ns);
    cudaGetSymbolAddress((void**)&p_nv,   g_nv);

    const float s128 = 0.08838834764831845f;   // 1/sqrt(128)
    const float s64  = 0.125f;                  // 1/sqrt(64)
    const float s192 = 0.07216878364870323f;    // 1/sqrt(192)

    detect_kernel<<<1, 32>>>(ei_raw);
    convert_kernel<<<512, 256>>>(ei_raw, 2 * E);

    prep_kernel<<<2048, 256>>>(x, N);

    // pre_s = xs @ Wpre_s * s128 + bpre_s
    gemm_kernel<<<dim3(2, N / 64), 256>>>(x, 320, Wpre_s, 128, p_pre_s,
                                          N, 128, 128, s128, bpre_s, 0, 0, 128, 0);
    // pre_v = xvT @ Wpre_v * s64   (M = 3N)
    gemm_kernel<<<dim3(1, 3 * N / 64), 256>>>(p_xvT, 64, Wpre_v, 64, p_pre_v,
                                              3 * N, 64, 64, s64, nullptr, 0, 0, 64, 0);
    // h1 = silu(f0 @ Wg1 + bg1)
    gemm_kernel<<<dim3(3, N / 64), 256>>>(p_f0, 192, Wg1, 192, p_h1,
                                          N, 192, 192, 1.f, bg1, 1, 0, 192, 0);
    // g = h1 @ Wg2 + bg2
    gemm_kernel<<<dim3(3, N / 64), 256>>>(p_h1, 192, Wg2, 192, p_g,
                                          N, 192, 192, 1.f, bg2, 0, 0, 192, 0);
    // xs3 = g[:, :128] @ Wn_s * s128 + bn_s
    gemm_kernel<<<dim3(2, N / 64), 256>>>(p_g, 192, Wn_s, 128, p_xs3,
                                          N, 128, 128, s128, bn_s, 0, 0, 128, 0);
    // xv2 = xv * gate
    gate_kernel<<<2048, 256>>>(N);
    // xv3 = xv2T @ Wn_v * s64
    gemm_kernel<<<dim3(1, 3 * N / 64), 256>>>(p_xv2T, 64, Wn_v, 64, p_xv3,
                                              3 * N, 64, 64, s64, nullptr, 0, 0, 64, 0);

    zero_kernel<<<2048, 256>>>(N);

    cudaFuncSetAttribute(edge_kernel, cudaFuncAttributeMaxDynamicSharedMemorySize,
                         EDGE_SMEM_BYTES);
    edge_kernel<<<152, ETHREADS, EDGE_SMEM_BYTES>>>(ea, esh, Wf1, Wf2, Wl1, Wl2, E, N);

    // outs -> d_out[:, 0:256]
    gemm_kernel<<<dim3(4, N / 64), 256>>>(p_ns, 192, Wo_s, 256, out,
                                          N, 192, 256, s192, bo_s, 0, 0, 640, 0);
    // outv (interleaved) -> d_out[:, 256:640]
    gemm_kernel<<<dim3(2, 3 * N / 64), 256>>>(p_nv, 192, Wo_v, 128, out,
                                              3 * N, 192, 128, s192, nullptr, 0, 1, 0, N);
}

// round 4
// speedup vs baseline: 1.9868x; 1.9868x over previous
#include <cuda_runtime.h>
#include <math.h>

#define NMAX 16000
#define EMAX 256000

// ---------------- static device scratch ----------------
__device__ float g_xvT [3*NMAX*64];
__device__ float g_f0  [NMAX*192];
__device__ float g_pre_s[NMAX*128];
__device__ float g_pre_v[3*NMAX*64];
__device__ float g_h1  [NMAX*192];
__device__ float g_g   [NMAX*192];
__device__ float g_xv2T[3*NMAX*64];
__device__ float g_xs3 [NMAX*128];
__device__ float g_xv3 [3*NMAX*64];
__device__ float g_ns  [NMAX*192];
__device__ float g_nv  [3*NMAX*192];
__device__ float g_nl1 [NMAX*32];     // pre_s @ (Wl1_a + Wl1_b)
__device__ float g_Wl1c[128*32];      // Wl1[0:128] + Wl1[128:256]
__device__ int   g_ei  [2*EMAX];
__device__ int   g_is64;

// ---------------- edge-index dtype detect/convert ----------------
__global__ void detect_kernel(const int* __restrict__ ei_raw) {
    if (threadIdx.x == 0 && blockIdx.x == 0) {
        int nz = 0;
        for (int i = 1; i < 256; i += 2) nz += (ei_raw[i] != 0);
        g_is64 = (nz == 0) ? 1 : 0;
    }
}
__global__ void convert_kernel(const int* __restrict__ ei_raw, int total) {
    int is64 = g_is64;
    for (int idx = blockIdx.x * blockDim.x + threadIdx.x; idx < total;
         idx += gridDim.x * blockDim.x)
        g_ei[idx] = is64 ? ei_raw[2 * idx] : ei_raw[idx];
}

// ---------------- prep ----------------
__global__ void prep_kernel(const float* __restrict__ x, int N) {
    int total = N * 192;
    for (int idx = blockIdx.x * blockDim.x + threadIdx.x; idx < total;
         idx += gridDim.x * blockDim.x) {
        int n = idx / 192, i = idx - n * 192;
        if (i < 128) {
            g_f0[n * 192 + i] = x[n * 320 + i];
        } else {
            int u = i - 128;
            float a = x[n * 320 + 128 + 3 * u + 0];
            float b = x[n * 320 + 128 + 3 * u + 1];
            float c = x[n * 320 + 128 + 3 * u + 2];
            g_xvT[(0 * N + n) * 64 + u] = a;
            g_xvT[(1 * N + n) * 64 + u] = b;
            g_xvT[(2 * N + n) * 64 + u] = c;
            g_f0[n * 192 + i] = sqrtf(a * a + b * b + c * c + 1e-12f);
        }
    }
}

__global__ void gate_kernel(int N) {
    int total = 3 * N * 64;
    for (int idx = blockIdx.x * blockDim.x + threadIdx.x; idx < total;
         idx += gridDim.x * blockDim.x) {
        int rem = idx % (N * 64);
        int n = rem / 64, u = rem - n * 64;
        g_xv2T[idx] = g_xvT[idx] * g_g[n * 192 + 128 + u];
    }
}

__global__ void zero_kernel(int N) {
    int t1 = N * 192, t2 = 3 * N * 192, total = t1 + t2;
    for (int idx = blockIdx.x * blockDim.x + threadIdx.x; idx < total;
         idx += gridDim.x * blockDim.x) {
        if (idx < t1) g_ns[idx] = 0.f;
        else          g_nv[idx - t1] = 0.f;
    }
}

// ---------------- Wl1 fold + per-node l1 partial ----------------
__global__ void wsum_kernel(const float* __restrict__ Wl1) {
    int idx = blockIdx.x * blockDim.x + threadIdx.x;
    if (idx < 128 * 32) g_Wl1c[idx] = Wl1[idx] + Wl1[128 * 32 + idx];
}

// node_l1[n][j] = sum_q pre_s[n][q] * Wl1c[q][j]   (unscaled)
__global__ void nl1_kernel(int N) {
    __shared__ float sW[128 * 32];
    int tid = threadIdx.x;
    for (int i = tid; i < 128 * 32; i += 256) sW[i] = g_Wl1c[i];
    __syncthreads();
    int j = tid & 31;
    int n = blockIdx.x * 8 + (tid >> 5);
    if (n >= N) return;
    const float* row = &g_pre_s[(size_t)n * 128];
    float acc = 0.f;
#pragma unroll 8
    for (int q = 0; q < 128; q++) acc += row[q] * sW[q * 32 + j];
    g_nl1[(size_t)n * 32 + j] = acc;
}

// ---------------- generic SGEMM (unchanged) ----------------
__global__ void gemm_kernel(const float* __restrict__ X, int ldx,
                            const float* __restrict__ W, int ldw,
                            float* __restrict__ C,
                            int M, int K, int O,
                            float scale, const float* __restrict__ bias,
                            int act, int out_mode, int ldc, int nnodes) {
    __shared__ __align__(16) float sX[16][64];
    __shared__ __align__(16) float sW[16][64];
    int bm = blockIdx.y * 64, bo = blockIdx.x * 64;
    int tid = threadIdx.x;
    int tr = tid >> 4, tc = tid & 15;
    float acc[4][4];
#pragma unroll
    for (int i = 0; i < 4; i++)
#pragma unroll
        for (int j = 0; j < 4; j++) acc[i][j] = 0.f;

    for (int k0 = 0; k0 < K; k0 += 16) {
#pragma unroll
        for (int l = 0; l < 4; l++) {
            int i = tid + l * 256;
            int r = i >> 4, c = i & 15;
            sX[c][r] = X[(long long)(bm + r) * ldx + k0 + c];
        }
#pragma unroll
        for (int l = 0; l < 4; l++) {
            int i = tid + l * 256;
            int r = i >> 6, c = i & 63;
            sW[r][c] = W[(k0 + r) * ldw + bo + c];
        }
        __syncthreads();
#pragma unroll
        for (int k = 0; k < 16; k++) {
            float4 xv4 = *reinterpret_cast<const float4*>(&sX[k][tr * 4]);
            float4 wv4 = *reinterpret_cast<const float4*>(&sW[k][tc * 4]);
            float xr[4] = {xv4.x, xv4.y, xv4.z, xv4.w};
            float wc[4] = {wv4.x, wv4.y, wv4.z, wv4.w};
#pragma unroll
            for (int i = 0; i < 4; i++)
#pragma unroll
                for (int j = 0; j < 4; j++) acc[i][j] += xr[i] * wc[j];
        }
        __syncthreads();
    }

#pragma unroll
    for (int i = 0; i < 4; i++) {
        int m = bm + tr * 4 + i;
#pragma unroll
        for (int j = 0; j < 4; j++) {
            int o = bo + tc * 4 + j;
            float v = acc[i][j] * scale;
            if (bias) v += bias[o];
            if (act == 1) v = v / (1.f + expf(-v));
            if (out_mode == 0) {
                C[(long long)m * ldc + o] = v;
            } else {
                int cc = m / nnodes;
                int n = m - cc * nnodes;
                C[(long long)n * 640 + 256 + o * 3 + cc] = v;
            }
        }
    }
}

// ---------------- vectorized global reduction ----------------
__device__ __forceinline__ void red4(float* addr, float a, float b, float c, float d) {
    asm volatile("red.global.add.v4.f32 [%0], {%1,%2,%3,%4};"
                 :: "l"(addr), "f"(a), "f"(b), "f"(c), "f"(d) : "memory");
}

__device__ __forceinline__ float ssp_f(float x) {
    const float ln2 = 0.69314718055994531f;
    return fmaxf(x, 0.f) + log1pf(expf(-fabsf(x))) - ln2;
}

// ---------------- fused edge kernel v2 ----------------
#define ETILE 64
#define ETHREADS 512
// shared floats:
// sWf1 1024 | sWf2 12288 | sWc 2048 | sWl2 12288 |
// sea 64*33 | snl 64*33 | sip 64*65 | shfT 32*64 | shlT 32*64 | ssh 256
#define OFF_WF1 0
#define OFF_WF2 (OFF_WF1 + 1024)
#define OFF_WC  (OFF_WF2 + 12288)
#define OFF_WL2 (OFF_WC + 2048)
#define OFF_EA  (OFF_WL2 + 12288)
#define OFF_NL  (OFF_EA + 64*33)
#define OFF_IP  (OFF_NL + 64*33)
#define OFF_HF  (OFF_IP + 64*65)
#define OFF_HL  (OFF_HF + 32*64)
#define OFF_SH  (OFF_HL + 32*64)
#define OFF_END (OFF_SH + 256)
#define EDGE_SMEM_BYTES (OFF_END*4 + 128*4)

__global__ void __launch_bounds__(ETHREADS, 1)
edge_kernel(const float* __restrict__ edge_attr,
            const float* __restrict__ edge_sh,
            const float* __restrict__ Wf1, const float* __restrict__ Wf2,
            const float* __restrict__ Wl1, const float* __restrict__ Wl2,
            int E, int N) {
    extern __shared__ float sm[];
    float* sWf1 = sm + OFF_WF1;
    float* sWf2 = sm + OFF_WF2;
    float* sWc  = sm + OFF_WC;
    float* sWl2 = sm + OFF_WL2;
    float* sea  = sm + OFF_EA;
    float* snl  = sm + OFF_NL;
    float* sip  = sm + OFF_IP;
    float* shfT = sm + OFF_HF;
    float* shlT = sm + OFF_HL;
    float* ssh  = sm + OFF_SH;
    int*   sidx = (int*)(sm + OFF_END);

    int tid = threadIdx.x;
    for (int i = tid; i < 1024;  i += ETHREADS) sWf1[i] = Wf1[i];
    for (int i = tid; i < 12288; i += ETHREADS) sWf2[i] = Wf2[i];
    for (int i = tid; i < 2048;  i += ETHREADS) sWc[i]  = Wl1[256 * 32 + i];
    for (int i = tid; i < 12288; i += ETHREADS) sWl2[i] = Wl2[i];

    const float c0 = 0.5f, c1 = 0.86602540378443865f;
    const float inv3 = 1.f / 3.f;
    const float inv32 = 0.03125f;                 // invs32^2
    const float invs32 = 0.17677669529663687f;
    const float invs320 = 0.05590169943749474f;
    const float invs3 = 0.57735026918962576f;

    int warp = tid >> 5, lane = tid & 31;
    int eb = warp * 4;

    int ntiles = (E + ETILE - 1) / ETILE;
    for (int tile = blockIdx.x; tile < ntiles; tile += gridDim.x) {
        int e0 = tile * ETILE;
        int cnt = min(ETILE, E - e0);
        __syncthreads();   // smem reuse fence (covers weight staging on 1st iter)

        if (tid < ETILE) {
            int valid = tid < cnt;
            sidx[tid]         = valid ? g_ei[e0 + tid]     : 0;
            sidx[ETILE + tid] = valid ? g_ei[E + e0 + tid] : 0;
        }
        if (tid >= 256 && tid < 512) {
            int i = tid - 256;
            int t = i >> 2, q = i & 3;
            ssh[i] = (t < cnt) ? edge_sh[(size_t)(e0 + t) * 4 + q] : 0.f;
        }
        for (int i = tid; i < 64 * 32; i += ETHREADS) {
            int t = i >> 5, q = i & 31;
            sea[t * 33 + q] = (t < cnt) ? edge_attr[(size_t)(e0 + t) * 32 + q] : 0.f;
        }
        __syncthreads();

        // sip[t][u] = (1/3) * sum_c pre_v[c][d][u] * pre_v[c][s][u]
        for (int i = tid; i < 64 * 64; i += ETHREADS) {
            int t = i >> 6, u = i & 63;
            int d = sidx[t], s = sidx[ETILE + t];
            float acc = 0.f;
#pragma unroll
            for (int c = 0; c < 3; c++)
                acc += g_pre_v[((size_t)c * N + d) * 64 + u] *
                       g_pre_v[((size_t)c * N + s) * 64 + u];
            sip[t * 65 + u] = acc * inv3;
        }
        // snl[t][j] = node_l1[dst][j]
        for (int i = tid; i < 64 * 32; i += ETHREADS) {
            int t = i >> 5, j = i & 31;
            int d = sidx[t];
            snl[t * 33 + j] = g_nl1[(size_t)d * 32 + j];
        }
        // hf transposed: shfT[j][t]
        for (int i = tid; i < 2048; i += ETHREADS) {
            int t = i & 63, j = i >> 6;
            float acc = 0.f;
#pragma unroll 8
            for (int q = 0; q < 32; q++) acc += sea[t * 33 + q] * sWf1[q * 32 + j];
            shfT[j * 64 + t] = ssp_f(acc * invs32);
        }
        __syncthreads();

        // hl transposed: shlT[j][t] = ssp((snl + ip @ Wc) * invs320)
        for (int i = tid; i < 2048; i += ETHREADS) {
            int t = i & 63, j = i >> 6;
            float acc = snl[t * 33 + j];
#pragma unroll 8
            for (int u = 0; u < 64; u++) acc += sip[t * 65 + u] * sWc[u * 32 + j];
            shlT[j * 64 + t] = ssp_f(acc * invs320);
        }
        __syncthreads();

        // layer 2: per thread 4 edges x 4 outputs, 3 output blocks
#pragma unroll 1
        for (int ob = 0; ob < 3; ob++) {
            int o0 = ob * 128 + lane * 4;
            float wf[4][4], wl[4][4];
#pragma unroll
            for (int a = 0; a < 4; a++)
#pragma unroll
                for (int b = 0; b < 4; b++) { wf[a][b] = 0.f; wl[a][b] = 0.f; }

#pragma unroll 2
            for (int j = 0; j < 32; j++) {
                float4 hf = *reinterpret_cast<const float4*>(&shfT[j * 64 + eb]);
                float4 hl = *reinterpret_cast<const float4*>(&shlT[j * 64 + eb]);
                float4 af = *reinterpret_cast<const float4*>(&sWf2[j * 384 + o0]);
                float4 al = *reinterpret_cast<const float4*>(&sWl2[j * 384 + o0]);
                float hfv[4] = {hf.x, hf.y, hf.z, hf.w};
                float hlv[4] = {hl.x, hl.y, hl.z, hl.w};
                float afv[4] = {af.x, af.y, af.z, af.w};
                float alv[4] = {al.x, al.y, al.z, al.w};
#pragma unroll
                for (int a = 0; a < 4; a++)
#pragma unroll
                    for (int b = 0; b < 4; b++) {
                        wf[a][b] += hfv[a] * afv[b];
                        wl[a][b] += hlv[a] * alv[b];
                    }
            }

            // epilogue: scatter
#pragma unroll
            for (int a = 0; a < 4; a++) {
                int t = eb + a;
                if (t >= cnt) continue;
                int d = sidx[t], s = sidx[ETILE + t];
                float sh0 = ssh[t * 4 + 0];
                float w0 = wf[a][0] * wl[a][0] * inv32;
                float w1 = wf[a][1] * wl[a][1] * inv32;
                float w2 = wf[a][2] * wl[a][2] * inv32;
                float w3 = wf[a][3] * wl[a][3] * inv32;
                if (o0 < 128) {
                    float4 hs = *reinterpret_cast<const float4*>(&g_xs3[(size_t)s * 128 + o0]);
                    float k = c0 * sh0;
                    red4(&g_ns[(size_t)d * 192 + o0],
                         k * w0 * hs.x, k * w1 * hs.y, k * w2 * hs.z, k * w3 * hs.w);
                } else if (o0 < 256) {
                    int u0 = o0 - 128;
                    float4 hs = *reinterpret_cast<const float4*>(&g_xs3[(size_t)s * 128 + u0]);
                    float b0 = c1 * w0 * hs.x, b1 = c1 * w1 * hs.y;
                    float b2 = c1 * w2 * hs.z, b3 = c1 * w3 * hs.w;
#pragma unroll
                    for (int c = 0; c < 3; c++) {
                        float shc = ssh[t * 4 + 1 + c];
                        red4(&g_nv[((size_t)c * N + d) * 192 + u0],
                             b0 * shc, b1 * shc, b2 * shc, b3 * shc);
                    }
                } else if (o0 < 320) {
                    int u0 = o0 - 256;
                    float b0 = c1 * w0 * sh0, b1 = c1 * w1 * sh0;
                    float b2 = c1 * w2 * sh0, b3 = c1 * w3 * sh0;
#pragma unroll
                    for (int c = 0; c < 3; c++) {
                        float4 hv = *reinterpret_cast<const float4*>(
                            &g_xv3[((size_t)c * N + s) * 64 + u0]);
                        red4(&g_nv[((size_t)c * N + d) * 192 + 128 + u0],
                             b0 * hv.x, b1 * hv.y, b2 * hv.z, b3 * hv.w);
                    }
                } else {
                    int u0 = o0 - 320;
                    float4 hx = *reinterpret_cast<const float4*>(&g_xv3[((size_t)0 * N + s) * 64 + u0]);
                    float4 hy = *reinterpret_cast<const float4*>(&g_xv3[((size_t)1 * N + s) * 64 + u0]);
                    float4 hz = *reinterpret_cast<const float4*>(&g_xv3[((size_t)2 * N + s) * 64 + u0]);
                    float sh1 = ssh[t * 4 + 1], sh2 = ssh[t * 4 + 2], sh3 = ssh[t * 4 + 3];
                    float k = c0 * invs3;
                    red4(&g_ns[(size_t)d * 192 + 128 + u0],
                         k * w0 * (hx.x * sh1 + hy.x * sh2 + hz.x * sh3),
                         k * w1 * (hx.y * sh1 + hy.y * sh2 + hz.y * sh3),
                         k * w2 * (hx.z * sh1 + hy.z * sh2 + hz.z * sh3),
                         k * w3 * (hx.w * sh1 + hy.w * sh2 + hz.w * sh3));
                }
            }
        }
    }
}

// ---------------- launch ----------------
extern "C" void kernel_launch(void* const* d_in, const int* in_sizes, int n_in,
                              void* d_out, int out_size) {
    const float* x      = (const float*)d_in[0];
    const int*   ei_raw = (const int*)d_in[1];
    const float* ea     = (const float*)d_in[2];
    const float* esh    = (const float*)d_in[3];
    const float* Wpre_s = (const float*)d_in[4];
    const float* bpre_s = (const float*)d_in[5];
    const float* Wpre_v = (const float*)d_in[6];
    const float* Wg1    = (const float*)d_in[7];
    const float* bg1    = (const float*)d_in[8];
    const float* Wg2    = (const float*)d_in[9];
    const float* bg2    = (const float*)d_in[10];
    const float* Wn_s   = (const float*)d_in[11];
    const float* bn_s   = (const float*)d_in[12];
    const float* Wn_v   = (const float*)d_in[13];
    const float* Wf1    = (const float*)d_in[14];
    const float* Wf2    = (const float*)d_in[15];
    const float* Wl1    = (const float*)d_in[16];
    const float* Wl2    = (const float*)d_in[17];
    const float* Wo_s   = (const float*)d_in[18];
    const float* bo_s   = (const float*)d_in[19];
    const float* Wo_v   = (const float*)d_in[20];

    int N = in_sizes[0] / 320;
    int E = in_sizes[1] / 2;
    float* out = (float*)d_out;

    float *p_xvT, *p_f0, *p_pre_s, *p_pre_v, *p_h1, *p_g, *p_xv2T, *p_xs3, *p_ns, *p_nv;
    cudaGetSymbolAddress((void**)&p_xvT,  g_xvT);
    cudaGetSymbolAddress((void**)&p_f0,   g_f0);
    cudaGetSymbolAddress((void**)&p_pre_s,g_pre_s);
    cudaGetSymbolAddress((void**)&p_pre_v,g_pre_v);
    cudaGetSymbolAddress((void**)&p_h1,   g_h1);
    cudaGetSymbolAddress((void**)&p_g,    g_g);
    cudaGetSymbolAddress((void**)&p_xv2T, g_xv2T);
    cudaGetSymbolAddress((void**)&p_xs3,  g_xs3);
    cudaGetSymbolAddress((void**)&p_ns,   g_ns);
    cudaGetSymbolAddress((void**)&p_nv,   g_nv);
    float* p_xv3; cudaGetSymbolAddress((void**)&p_xv3, g_xv3);

    const float s128 = 0.08838834764831845f;
    const float s64  = 0.125f;
    const float s192 = 0.07216878364870323f;

    detect_kernel<<<1, 32>>>(ei_raw);
    convert_kernel<<<512, 256>>>(ei_raw, 2 * E);
    prep_kernel<<<2048, 256>>>(x, N);

    gemm_kernel<<<dim3(2, N / 64), 256>>>(x, 320, Wpre_s, 128, p_pre_s,
                                          N, 128, 128, s128, bpre_s, 0, 0, 128, 0);
    gemm_kernel<<<dim3(1, 3 * N / 64), 256>>>(p_xvT, 64, Wpre_v, 64, p_pre_v,
                                              3 * N, 64, 64, s64, nullptr, 0, 0, 64, 0);
    gemm_kernel<<<dim3(3, N / 64), 256>>>(p_f0, 192, Wg1, 192, p_h1,
                                          N, 192, 192, 1.f, bg1, 1, 0, 192, 0);
    gemm_kernel<<<dim3(3, N / 64), 256>>>(p_h1, 192, Wg2, 192, p_g,
                                          N, 192, 192, 1.f, bg2, 0, 0, 192, 0);
    gemm_kernel<<<dim3(2, N / 64), 256>>>(p_g, 192, Wn_s, 128, p_xs3,
                                          N, 128, 128, s128, bn_s, 0, 0, 128, 0);
    gate_kernel<<<2048, 256>>>(N);
    gemm_kernel<<<dim3(1, 3 * N / 64), 256>>>(p_xv2T, 64, Wn_v, 64, p_xv3,
                                              3 * N, 64, 64, s64, nullptr, 0, 0, 64, 0);

    wsum_kernel<<<16, 256>>>(Wl1);
    nl1_kernel<<<(N + 7) / 8, 256>>>(N);

    zero_kernel<<<2048, 256>>>(N);

    cudaFuncSetAttribute(edge_kernel, cudaFuncAttributeMaxDynamicSharedMemorySize,
                         EDGE_SMEM_BYTES);
    edge_kernel<<<148, ETHREADS, EDGE_SMEM_BYTES>>>(ea, esh, Wf1, Wf2, Wl1, Wl2, E, N);

    gemm_kernel<<<dim3(4, N / 64), 256>>>(p_ns, 192, Wo_s, 256, out,
                                          N, 192, 256, s192, bo_s, 0, 0, 640, 0);
    gemm_kernel<<<dim3(2, 3 * N / 64), 256>>>(p_nv, 192, Wo_v, 128, out,
                                              3 * N, 192, 128, s192, nullptr, 0, 1, 0, N);
}

// round 5
// speedup vs baseline: 2.3314x; 1.1734x over previous
#include <cuda_runtime.h>
#include <math.h>

#define NMAX 16000
#define EMAX 256000

// ---------------- static device scratch ----------------
__device__ float g_xvT [3*NMAX*64];
__device__ float g_f0  [NMAX*192];
__device__ float g_pre_s[NMAX*128];
__device__ float g_pre_v[3*NMAX*64];
__device__ float g_h1  [NMAX*192];
__device__ float g_g   [NMAX*192];
__device__ float g_xv2T[3*NMAX*64];
__device__ float g_xs3 [NMAX*128];
__device__ float g_xv3 [3*NMAX*64];
__device__ float g_ns  [NMAX*192];
__device__ float g_nv  [3*NMAX*192];
__device__ float g_nl1 [NMAX*32];
__device__ float g_Wl1c[128*32];
__device__ int   g_ei  [2*EMAX];
__device__ int   g_is64;

// ---------------- edge-index dtype detect/convert ----------------
__global__ void detect_kernel(const int* __restrict__ ei_raw) {
    if (threadIdx.x == 0 && blockIdx.x == 0) {
        int nz = 0;
        for (int i = 1; i < 256; i += 2) nz += (ei_raw[i] != 0);
        g_is64 = (nz == 0) ? 1 : 0;
    }
}
__global__ void convert_kernel(const int* __restrict__ ei_raw, int total) {
    int is64 = g_is64;
    for (int idx = blockIdx.x * blockDim.x + threadIdx.x; idx < total;
         idx += gridDim.x * blockDim.x)
        g_ei[idx] = is64 ? ei_raw[2 * idx] : ei_raw[idx];
}

// ---------------- prep ----------------
__global__ void prep_kernel(const float* __restrict__ x, int N) {
    int total = N * 192;
    for (int idx = blockIdx.x * blockDim.x + threadIdx.x; idx < total;
         idx += gridDim.x * blockDim.x) {
        int n = idx / 192, i = idx - n * 192;
        if (i < 128) {
            g_f0[n * 192 + i] = x[n * 320 + i];
        } else {
            int u = i - 128;
            float a = x[n * 320 + 128 + 3 * u + 0];
            float b = x[n * 320 + 128 + 3 * u + 1];
            float c = x[n * 320 + 128 + 3 * u + 2];
            g_xvT[(0 * N + n) * 64 + u] = a;
            g_xvT[(1 * N + n) * 64 + u] = b;
            g_xvT[(2 * N + n) * 64 + u] = c;
            g_f0[n * 192 + i] = sqrtf(a * a + b * b + c * c + 1e-12f);
        }
    }
}

__global__ void gate_kernel(int N) {
    int total = 3 * N * 64;
    for (int idx = blockIdx.x * blockDim.x + threadIdx.x; idx < total;
         idx += gridDim.x * blockDim.x) {
        int rem = idx % (N * 64);
        int n = rem / 64, u = rem - n * 64;
        g_xv2T[idx] = g_xvT[idx] * g_g[n * 192 + 128 + u];
    }
}

__global__ void zero_kernel(int N) {
    int t1 = N * 192, t2 = 3 * N * 192, total = t1 + t2;
    for (int idx = blockIdx.x * blockDim.x + threadIdx.x; idx < total;
         idx += gridDim.x * blockDim.x) {
        if (idx < t1) g_ns[idx] = 0.f;
        else          g_nv[idx - t1] = 0.f;
    }
}

// ---------------- Wl1 fold + per-node l1 partial ----------------
__global__ void wsum_kernel(const float* __restrict__ Wl1) {
    int idx = blockIdx.x * blockDim.x + threadIdx.x;
    if (idx < 128 * 32) g_Wl1c[idx] = Wl1[idx] + Wl1[128 * 32 + idx];
}

__global__ void nl1_kernel(int N) {
    __shared__ float sW[128 * 32];
    int tid = threadIdx.x;
    for (int i = tid; i < 128 * 32; i += 256) sW[i] = g_Wl1c[i];
    __syncthreads();
    int j = tid & 31;
    int n = blockIdx.x * 8 + (tid >> 5);
    if (n >= N) return;
    const float* row = &g_pre_s[(size_t)n * 128];
    float acc = 0.f;
#pragma unroll 8
    for (int q = 0; q < 128; q++) acc += row[q] * sW[q * 32 + j];
    g_nl1[(size_t)n * 32 + j] = acc;
}

// ---------------- SGEMM v2: BM=128 BN=64 BK=16, 8x4/thread, double-buffered ----------------
// Requires M % 128 == 0, O % 64 == 0, K % 16 == 0 (true for all uses).
__global__ void __launch_bounds__(256)
gemm_kernel(const float* __restrict__ X, int ldx,
            const float* __restrict__ W, int ldw,
            float* __restrict__ C,
            int M, int K, int O,
            float scale, const float* __restrict__ bias,
            int act, int out_mode, int ldc, int nnodes) {
    __shared__ __align__(16) float sX[2][16][132];
    __shared__ __align__(16) float sW[2][16][68];
    int bm = blockIdx.y * 128, bo = blockIdx.x * 64;
    int tid = threadIdx.x;
    int tr = tid >> 4, tc = tid & 15;       // tr 0..15 (8 rows each), tc 0..15 (4 cols)
    int m0 = tr * 8, o0 = tc * 4;

    float acc[8][4];
#pragma unroll
    for (int i = 0; i < 8; i++)
#pragma unroll
        for (int j = 0; j < 4; j++) acc[i][j] = 0.f;

    // per-thread load coordinates
    int xr[8], xc[8];
#pragma unroll
    for (int l = 0; l < 8; l++) {
        int i = tid + l * 256;
        xr[l] = i >> 4;          // row 0..127
        xc[l] = i & 15;          // col 0..15
    }
    int wr[4], wc[4];
#pragma unroll
    for (int l = 0; l < 4; l++) {
        int i = tid + l * 256;
        wr[l] = i >> 6;          // row 0..15
        wc[l] = i & 63;          // col 0..63
    }

    int ntiles = K >> 4;
    float rx[8], rw[4];
    // prefetch tile 0
#pragma unroll
    for (int l = 0; l < 8; l++)
        rx[l] = X[(long long)(bm + xr[l]) * ldx + xc[l]];
#pragma unroll
    for (int l = 0; l < 4; l++)
        rw[l] = W[(long long)wr[l] * ldw + bo + wc[l]];

    for (int t = 0; t < ntiles; t++) {
        int buf = t & 1;
#pragma unroll
        for (int l = 0; l < 8; l++) sX[buf][xc[l]][xr[l]] = rx[l];
#pragma unroll
        for (int l = 0; l < 4; l++) sW[buf][wr[l]][wc[l]] = rw[l];
        __syncthreads();
        if (t + 1 < ntiles) {
            int k0 = (t + 1) << 4;
#pragma unroll
            for (int l = 0; l < 8; l++)
                rx[l] = X[(long long)(bm + xr[l]) * ldx + k0 + xc[l]];
#pragma unroll
            for (int l = 0; l < 4; l++)
                rw[l] = W[(long long)(k0 + wr[l]) * ldw + bo + wc[l]];
        }
#pragma unroll
        for (int k = 0; k < 16; k++) {
            float4 a0 = *reinterpret_cast<const float4*>(&sX[buf][k][m0]);
            float4 a1 = *reinterpret_cast<const float4*>(&sX[buf][k][m0 + 4]);
            float4 b  = *reinterpret_cast<const float4*>(&sW[buf][k][o0]);
            float av[8] = {a0.x, a0.y, a0.z, a0.w, a1.x, a1.y, a1.z, a1.w};
            float bv[4] = {b.x, b.y, b.z, b.w};
#pragma unroll
            for (int i = 0; i < 8; i++)
#pragma unroll
                for (int j = 0; j < 4; j++) acc[i][j] += av[i] * bv[j];
        }
        __syncthreads();
    }

#pragma unroll
    for (int i = 0; i < 8; i++) {
        int m = bm + m0 + i;
#pragma unroll
        for (int j = 0; j < 4; j++) {
            int o = bo + o0 + j;
            float v = acc[i][j] * scale;
            if (bias) v += bias[o];
            if (act == 1) v = v / (1.f + expf(-v));
            if (out_mode == 0) {
                C[(long long)m * ldc + o] = v;
            } else {
                int cc = m / nnodes;
                int n = m - cc * nnodes;
                C[(long long)n * 640 + 256 + o * 3 + cc] = v;
            }
        }
    }
}

// ---------------- vectorized global reduction ----------------
__device__ __forceinline__ void red4(float* addr, float a, float b, float c, float d) {
    asm volatile("red.global.add.v4.f32 [%0], {%1,%2,%3,%4};"
                 :: "l"(addr), "f"(a), "f"(b), "f"(c), "f"(d) : "memory");
}

__device__ __forceinline__ float ssp_f(float x) {
    const float ln2 = 0.69314718055994531f;
    return fmaxf(x, 0.f) + log1pf(expf(-fabsf(x))) - ln2;
}

// ---------------- fused edge kernel v3: 96 edges/tile, 768 threads ----------------
#define ETILE 96
#define ETHREADS 768
#define OFF_WF1 0
#define OFF_WF2 (OFF_WF1 + 1024)
#define OFF_WC  (OFF_WF2 + 12288)
#define OFF_WL2 (OFF_WC + 2048)
#define OFF_EA  (OFF_WL2 + 12288)
#define OFF_NL  (OFF_EA + 96*33)
#define OFF_IP  (OFF_NL + 96*33)
#define OFF_HF  (OFF_IP + 96*65)
#define OFF_HL  (OFF_HF + 32*96)
#define OFF_SH  (OFF_HL + 32*96)
#define OFF_END (OFF_SH + 384)
#define EDGE_SMEM_BYTES (OFF_END*4 + 192*4)

__global__ void __launch_bounds__(ETHREADS, 1)
edge_kernel(const float* __restrict__ edge_attr,
            const float* __restrict__ edge_sh,
            const float* __restrict__ Wf1, const float* __restrict__ Wf2,
            const float* __restrict__ Wl1, const float* __restrict__ Wl2,
            int E, int N) {
    extern __shared__ float sm[];
    float* sWf1 = sm + OFF_WF1;
    float* sWf2 = sm + OFF_WF2;
    float* sWc  = sm + OFF_WC;
    float* sWl2 = sm + OFF_WL2;
    float* sea  = sm + OFF_EA;
    float* snl  = sm + OFF_NL;
    float* sip  = sm + OFF_IP;
    float* shfT = sm + OFF_HF;
    float* shlT = sm + OFF_HL;
    float* ssh  = sm + OFF_SH;
    int*   sidx = (int*)(sm + OFF_END);

    int tid = threadIdx.x;
    for (int i = tid; i < 1024;  i += ETHREADS) sWf1[i] = Wf1[i];
    for (int i = tid; i < 12288; i += ETHREADS) sWf2[i] = Wf2[i];
    for (int i = tid; i < 2048;  i += ETHREADS) sWc[i]  = Wl1[256 * 32 + i];
    for (int i = tid; i < 12288; i += ETHREADS) sWl2[i] = Wl2[i];

    const float c0 = 0.5f, c1 = 0.86602540378443865f;
    const float inv3 = 1.f / 3.f;
    const float inv32 = 0.03125f;
    const float invs32 = 0.17677669529663687f;
    const float invs320 = 0.05590169943749474f;
    const float invs3 = 0.57735026918962576f;

    int warp = tid >> 5, lane = tid & 31;
    int eb = warp * 4;

    int ntiles = (E + ETILE - 1) / ETILE;
    for (int tile = blockIdx.x; tile < ntiles; tile += gridDim.x) {
        int e0 = tile * ETILE;
        int cnt = min(ETILE, E - e0);
        __syncthreads();   // smem reuse fence (covers weight staging on 1st iter)

        if (tid < ETILE) {
            int valid = tid < cnt;
            sidx[tid]         = valid ? g_ei[e0 + tid]     : 0;
            sidx[ETILE + tid] = valid ? g_ei[E + e0 + tid] : 0;
        }
        for (int i = tid; i < ETILE * 4; i += ETHREADS) {
            int t = i >> 2, q = i & 3;
            ssh[i] = (t < cnt) ? edge_sh[(size_t)(e0 + t) * 4 + q] : 0.f;
        }
        for (int i = tid; i < ETILE * 32; i += ETHREADS) {
            int t = i >> 5, q = i & 31;
            sea[t * 33 + q] = (t < cnt) ? edge_attr[(size_t)(e0 + t) * 32 + q] : 0.f;
        }
        __syncthreads();

        // sip[t][u] = (1/3) * sum_c pre_v[c][d][u] * pre_v[c][s][u]
        for (int i = tid; i < ETILE * 64; i += ETHREADS) {
            int t = i >> 6, u = i & 63;
            int d = sidx[t], s = sidx[ETILE + t];
            float acc = 0.f;
#pragma unroll
            for (int c = 0; c < 3; c++)
                acc += g_pre_v[((size_t)c * N + d) * 64 + u] *
                       g_pre_v[((size_t)c * N + s) * 64 + u];
            sip[t * 65 + u] = acc * inv3;
        }
        // snl[t][j] = node_l1[dst][j]
        for (int i = tid; i < ETILE * 32; i += ETHREADS) {
            int t = i >> 5, j = i & 31;
            snl[t * 33 + j] = g_nl1[(size_t)sidx[t] * 32 + j];
        }
        // hf transposed: shfT[j][t]
        for (int i = tid; i < 32 * ETILE; i += ETHREADS) {
            int t = i % ETILE, j = i / ETILE;
            float acc = 0.f;
#pragma unroll 8
            for (int q = 0; q < 32; q++) acc += sea[t * 33 + q] * sWf1[q * 32 + j];
            shfT[j * ETILE + t] = ssp_f(acc * invs32);
        }
        __syncthreads();

        // hl transposed: shlT[j][t] = ssp((snl + ip @ Wc) * invs320)
        for (int i = tid; i < 32 * ETILE; i += ETHREADS) {
            int t = i % ETILE, j = i / ETILE;
            float acc = snl[t * 33 + j];
#pragma unroll 8
            for (int u = 0; u < 64; u++) acc += sip[t * 65 + u] * sWc[u * 32 + j];
            shlT[j * ETILE + t] = ssp_f(acc * invs320);
        }
        __syncthreads();

        // layer 2: per thread 4 edges x 4 outputs, 3 output blocks
#pragma unroll 1
        for (int ob = 0; ob < 3; ob++) {
            int o0 = ob * 128 + lane * 4;
            float wf[4][4], wl[4][4];
#pragma unroll
            for (int a = 0; a < 4; a++)
#pragma unroll
                for (int b = 0; b < 4; b++) { wf[a][b] = 0.f; wl[a][b] = 0.f; }

#pragma unroll 2
            for (int j = 0; j < 32; j++) {
                float4 hf = *reinterpret_cast<const float4*>(&shfT[j * ETILE + eb]);
                float4 hl = *reinterpret_cast<const float4*>(&shlT[j * ETILE + eb]);
                float4 af = *reinterpret_cast<const float4*>(&sWf2[j * 384 + o0]);
                float4 al = *reinterpret_cast<const float4*>(&sWl2[j * 384 + o0]);
                float hfv[4] = {hf.x, hf.y, hf.z, hf.w};
                float hlv[4] = {hl.x, hl.y, hl.z, hl.w};
                float afv[4] = {af.x, af.y, af.z, af.w};
                float alv[4] = {al.x, al.y, al.z, al.w};
#pragma unroll
                for (int a = 0; a < 4; a++)
#pragma unroll
                    for (int b = 0; b < 4; b++) {
                        wf[a][b] += hfv[a] * afv[b];
                        wl[a][b] += hlv[a] * alv[b];
                    }
            }

#pragma unroll
            for (int a = 0; a < 4; a++) {
                int t = eb + a;
                if (t >= cnt) continue;
                int d = sidx[t], s = sidx[ETILE + t];
                float sh0 = ssh[t * 4 + 0];
                float w0 = wf[a][0] * wl[a][0] * inv32;
                float w1 = wf[a][1] * wl[a][1] * inv32;
                float w2 = wf[a][2] * wl[a][2] * inv32;
                float w3 = wf[a][3] * wl[a][3] * inv32;
                if (o0 < 128) {
                    float4 hs = *reinterpret_cast<const float4*>(&g_xs3[(size_t)s * 128 + o0]);
                    float k = c0 * sh0;
                    red4(&g_ns[(size_t)d * 192 + o0],
                         k * w0 * hs.x, k * w1 * hs.y, k * w2 * hs.z, k * w3 * hs.w);
                } else if (o0 < 256) {
                    int u0 = o0 - 128;
                    float4 hs = *reinterpret_cast<const float4*>(&g_xs3[(size_t)s * 128 + u0]);
                    float b0 = c1 * w0 * hs.x, b1 = c1 * w1 * hs.y;
                    float b2 = c1 * w2 * hs.z, b3 = c1 * w3 * hs.w;
#pragma unroll
                    for (int c = 0; c < 3; c++) {
                        float shc = ssh[t * 4 + 1 + c];
                        red4(&g_nv[((size_t)c * N + d) * 192 + u0],
                             b0 * shc, b1 * shc, b2 * shc, b3 * shc);
                    }
                } else if (o0 < 320) {
                    int u0 = o0 - 256;
                    float b0 = c1 * w0 * sh0, b1 = c1 * w1 * sh0;
                    float b2 = c1 * w2 * sh0, b3 = c1 * w3 * sh0;
#pragma unroll
                    for (int c = 0; c < 3; c++) {
                        float4 hv = *reinterpret_cast<const float4*>(
                            &g_xv3[((size_t)c * N + s) * 64 + u0]);
                        red4(&g_nv[((size_t)c * N + d) * 192 + 128 + u0],
                             b0 * hv.x, b1 * hv.y, b2 * hv.z, b3 * hv.w);
                    }
                } else {
                    int u0 = o0 - 320;
                    float4 hx = *reinterpret_cast<const float4*>(&g_xv3[((size_t)0 * N + s) * 64 + u0]);
                    float4 hy = *reinterpret_cast<const float4*>(&g_xv3[((size_t)1 * N + s) * 64 + u0]);
                    float4 hz = *reinterpret_cast<const float4*>(&g_xv3[((size_t)2 * N + s) * 64 + u0]);
                    float sh1 = ssh[t * 4 + 1], sh2 = ssh[t * 4 + 2], sh3 = ssh[t * 4 + 3];
                    float k = c0 * invs3;
                    red4(&g_ns[(size_t)d * 192 + 128 + u0],
                         k * w0 * (hx.x * sh1 + hy.x * sh2 + hz.x * sh3),
                         k * w1 * (hx.y * sh1 + hy.y * sh2 + hz.y * sh3),
                         k * w2 * (hx.z * sh1 + hy.z * sh2 + hz.z * sh3),
                         k * w3 * (hx.w * sh1 + hy.w * sh2 + hz.w * sh3));
                }
            }
        }
    }
}

// ---------------- launch ----------------
extern "C" void kernel_launch(void* const* d_in, const int* in_sizes, int n_in,
                              void* d_out, int out_size) {
    const float* x      = (const float*)d_in[0];
    const int*   ei_raw = (const int*)d_in[1];
    const float* ea     = (const float*)d_in[2];
    const float* esh    = (const float*)d_in[3];
    const float* Wpre_s = (const float*)d_in[4];
    const float* bpre_s = (const float*)d_in[5];
    const float* Wpre_v = (const float*)d_in[6];
    const float* Wg1    = (const float*)d_in[7];
    const float* bg1    = (const float*)d_in[8];
    const float* Wg2    = (const float*)d_in[9];
    const float* bg2    = (const float*)d_in[10];
    const float* Wn_s   = (const float*)d_in[11];
    const float* bn_s   = (const float*)d_in[12];
    const float* Wn_v   = (const float*)d_in[13];
    const float* Wf1    = (const float*)d_in[14];
    const float* Wf2    = (const float*)d_in[15];
    const float* Wl1    = (const float*)d_in[16];
    const float* Wl2    = (const float*)d_in[17];
    const float* Wo_s   = (const float*)d_in[18];
    const float* bo_s   = (const float*)d_in[19];
    const float* Wo_v   = (const float*)d_in[20];

    int N = in_sizes[0] / 320;
    int E = in_sizes[1] / 2;
    float* out = (float*)d_out;

    float *p_xvT, *p_f0, *p_pre_s, *p_pre_v, *p_h1, *p_g, *p_xv2T, *p_xs3, *p_ns, *p_nv, *p_xv3;
    cudaGetSymbolAddress((void**)&p_xvT,  g_xvT);
    cudaGetSymbolAddress((void**)&p_f0,   g_f0);
    cudaGetSymbolAddress((void**)&p_pre_s,g_pre_s);
    cudaGetSymbolAddress((void**)&p_pre_v,g_pre_v);
    cudaGetSymbolAddress((void**)&p_h1,   g_h1);
    cudaGetSymbolAddress((void**)&p_g,    g_g);
    cudaGetSymbolAddress((void**)&p_xv2T, g_xv2T);
    cudaGetSymbolAddress((void**)&p_xs3,  g_xs3);
    cudaGetSymbolAddress((void**)&p_ns,   g_ns);
    cudaGetSymbolAddress((void**)&p_nv,   g_nv);
    cudaGetSymbolAddress((void**)&p_xv3,  g_xv3);

    const float s128 = 0.08838834764831845f;
    const float s64  = 0.125f;
    const float s192 = 0.07216878364870323f;

    detect_kernel<<<1, 32>>>(ei_raw);
    convert_kernel<<<512, 256>>>(ei_raw, 2 * E);
    prep_kernel<<<2048, 256>>>(x, N);

    gemm_kernel<<<dim3(2, N / 128), 256>>>(x, 320, Wpre_s, 128, p_pre_s,
                                           N, 128, 128, s128, bpre_s, 0, 0, 128, 0);
    gemm_kernel<<<dim3(1, 3 * N / 128), 256>>>(p_xvT, 64, Wpre_v, 64, p_pre_v,
                                               3 * N, 64, 64, s64, nullptr, 0, 0, 64, 0);
    gemm_kernel<<<dim3(3, N / 128), 256>>>(p_f0, 192, Wg1, 192, p_h1,
                                           N, 192, 192, 1.f, bg1, 1, 0, 192, 0);
    gemm_kernel<<<dim3(3, N / 128), 256>>>(p_h1, 192, Wg2, 192, p_g,
                                           N, 192, 192, 1.f, bg2, 0, 0, 192, 0);
    gemm_kernel<<<dim3(2, N / 128), 256>>>(p_g, 192, Wn_s, 128, p_xs3,
                                           N, 128, 128, s128, bn_s, 0, 0, 128, 0);
    gate_kernel<<<2048, 256>>>(N);
    gemm_kernel<<<dim3(1, 3 * N / 128), 256>>>(p_xv2T, 64, Wn_v, 64, p_xv3,
                                               3 * N, 64, 64, s64, nullptr, 0, 0, 64, 0);

    wsum_kernel<<<16, 256>>>(Wl1);
    nl1_kernel<<<(N + 7) / 8, 256>>>(N);

    zero_kernel<<<2048, 256>>>(N);

    cudaFuncSetAttribute(edge_kernel, cudaFuncAttributeMaxDynamicSharedMemorySize,
                         EDGE_SMEM_BYTES);
    edge_kernel<<<148, ETHREADS, EDGE_SMEM_BYTES>>>(ea, esh, Wf1, Wf2, Wl1, Wl2, E, N);

    gemm_kernel<<<dim3(4, N / 128), 256>>>(p_ns, 192, Wo_s, 256, out,
                                           N, 192, 256, s192, bo_s, 0, 0, 640, 0);
    gemm_kernel<<<dim3(2, 3 * N / 128), 256>>>(p_nv, 192, Wo_v, 128, out,
                                               3 * N, 192, 128, s192, nullptr, 0, 1, 0, N);
}